// round 10
// baseline (speedup 1.0000x reference)
#include <cuda_runtime.h>
#include <cuda_fp16.h>
#include <stdint.h>
#include <math.h>

#define NTOK 2048
#define EDIM 1024
#define NLAYER 4

// ---------------------------------------------------------------------------
// Scratch (device globals — allocation is forbidden). Pure fp16 operands.
// ---------------------------------------------------------------------------
__device__ __half g_x[NTOK * EDIM];
__device__ __half g_qkv[NTOK * 3 * EDIM];
__device__ float  g_p0[NTOK * 3 * EDIM];   // split-K partial 0 (24MB, reused)
__device__ float  g_p1[NTOK * 3 * EDIM];   // split-K partial 1
__device__ __half g_wh[NTOK * NTOK];
__device__ __half g_vT[EDIM * NTOK];
__device__ __half g_wv[NTOK * EDIM];
__device__ __half g_Wqkv[NLAYER * 3 * EDIM * EDIM];
__device__ __half g_Wo[NLAYER * EDIM * EDIM];
__device__ int    g_cnt[16 * 24];          // split-K arrival counters (self-resetting)

// ---------------------------------------------------------------------------
// Helpers
// ---------------------------------------------------------------------------
__device__ __forceinline__ uint32_t s2u(const void* p) {
    uint32_t a;
    asm("{ .reg .u64 t; cvta.to.shared.u64 t, %1; cvt.u32.u64 %0, t; }" : "=r"(a) : "l"(p));
    return a;
}
#define CPA(sm, gp) \
    asm volatile("cp.async.cg.shared.global [%0], [%1], 16;" :: "r"(sm), "l"(gp))
#define CPA_COMMIT() asm volatile("cp.async.commit_group;")
#define CPA_WAIT2()  asm volatile("cp.async.wait_group 2;")

#define LDSM4(r0, r1, r2, r3, addr)                                          \
    asm volatile("ldmatrix.sync.aligned.m8n8.x4.shared.b16 {%0,%1,%2,%3}, [%4];" \
                 : "=r"(r0), "=r"(r1), "=r"(r2), "=r"(r3) : "r"(addr))

__device__ __forceinline__ void mma16816(float* c, const uint32_t* a, const uint32_t* b) {
    asm volatile(
        "mma.sync.aligned.m16n8k16.row.col.f32.f16.f16.f32 "
        "{%0,%1,%2,%3}, {%4,%5,%6,%7}, {%8,%9}, {%0,%1,%2,%3};"
        : "+f"(c[0]), "+f"(c[1]), "+f"(c[2]), "+f"(c[3])
        : "r"(a[0]), "r"(a[1]), "r"(a[2]), "r"(a[3]), "r"(b[0]), "r"(b[1]));
}

__device__ __forceinline__ uint32_t pack2h(float a, float b) {
    __half2 t = __floats2half2_rn(a, b);
    return *reinterpret_cast<uint32_t*>(&t);
}

// SMEM: 4 stages; stage = 2 tiles (A, B) of 128 rows x 16 fp16,
// 48B pitch (banks 12r mod 32 distinct for r=0..7 -> conflict-free ldmatrix).
// (R8 configuration: best measured.)
#define TILE_B   6144          // 128 * 48
#define STAGE_B  12288         // 2 tiles
#define SMEM_BYTES (4 * STAGE_B)   // 49152

// ---------------------------------------------------------------------------
// Split-K (x2) tensor-core NT GEMM, single-pass fp16.
//   EPI 0: write fp32 partial to Cf0/Cf1 (consumed by softmax)
//   EPI 1: fused serial split-K reduction -> fp16 Dst (+bias), counter-gated
//   CSKIP: skip blocks strictly above diagonal;  KLIM: Keff = (by+1)*128
// 4-stage cp.async pipeline, ONE __syncthreads per K=16 chunk.
// ---------------------------------------------------------------------------
template<int EPI, bool CSKIP, bool KLIM>
__global__ void __launch_bounds__(256, 2) gemm_mma(
    const __half* __restrict__ A, int lda,
    const __half* __restrict__ B, int ldb,
    float* __restrict__ Cf0, float* __restrict__ Cf1, int ldc,
    __half* __restrict__ Dst, const float* __restrict__ bias,
    int* __restrict__ cnt,
    int K, float alpha)
{
    const int bx = blockIdx.x, by = blockIdx.y, kz = blockIdx.z;
    if (CSKIP && bx > by) return;
    const int Keff = KLIM ? min(K, (by + 1) * 128) : K;
    const int half = Keff >> 1;            // multiple of 64
    const int k0   = kz ? half : 0;
    const int nch  = half / 16;            // >= 4 in all uses

    float* __restrict__ Cp = kz ? Cf1 : Cf0;

    extern __shared__ __align__(128) char smem[];
    const uint32_t sb = s2u(smem);

    const int tid  = threadIdx.x;
    const int wid  = tid >> 5, lane = tid & 31;
    const int wm   = (wid & 1) * 64;       // warp m offset (2 warps)
    const int wn   = (wid >> 1) * 32;      // warp n offset (4 warps)

    const __half* Ab = A + (size_t)(by * 128) * lda;
    const __half* Bb = B + (size_t)(bx * 128) * ldb;

    // ldmatrix per-lane address components
    const uint32_t a_row = lane & 15;
    const uint32_t a_k   = (lane >> 4) * 16;
    const uint32_t b_row = (lane & 7) + (lane >> 4) * 8;
    const uint32_t b_k   = ((lane >> 3) & 1) * 16;

    float acc[4][4][4];
#pragma unroll
    for (int i = 0; i < 4; i++)
#pragma unroll
        for (int j = 0; j < 4; j++)
#pragma unroll
            for (int r = 0; r < 4; r++) acc[i][j][r] = 0.f;

    // per-thread loader slot: one 16B vector per tile
    const int lrow = tid >> 1;             // 0..127
    const int lc   = tid & 1;              // 0..1
    const uint32_t lso = (uint32_t)lrow * 48 + lc * 16;
    const size_t   lga = (size_t)lrow * lda + lc * 8;
    const size_t   lgb = (size_t)lrow * ldb + lc * 8;

    auto load_stage = [&](int stage, int kt) {
        uint32_t base = sb + (uint32_t)stage * STAGE_B + lso;
        CPA(base,          Ab + lga + kt);
        CPA(base + TILE_B, Bb + lgb + kt);
    };

    // prologue: stages 0..2 (nch >= 4 always)
#pragma unroll
    for (int s = 0; s < 3; s++) { load_stage(s, k0 + s * 16); CPA_COMMIT(); }

    for (int c = 0; c < nch; c++) {
        CPA_WAIT2();            // chunk c's group complete (<=2 newer pending)
        __syncthreads();        // data visible + all warps done with stage c-1
        if (c + 3 < nch) load_stage((c + 3) & 3, k0 + (c + 3) * 16);
        CPA_COMMIT();           // uniform commit keeps group counting simple

        const uint32_t base = sb + (uint32_t)(c & 3) * STAGE_B;

        uint32_t bf[8];
        {
            uint32_t bb = base + TILE_B + (wn + b_row) * 48 + b_k;
            LDSM4(bf[0], bf[1], bf[2], bf[3], bb);
            LDSM4(bf[4], bf[5], bf[6], bf[7], bb + 16 * 48);
        }
#pragma unroll
        for (int mf = 0; mf < 4; mf++) {
            uint32_t ah[4];
            uint32_t ab = base + (wm + mf * 16 + a_row) * 48 + a_k;
            LDSM4(ah[0], ah[1], ah[2], ah[3], ab);
#pragma unroll
            for (int nf = 0; nf < 4; nf++)
                mma16816(acc[mf][nf], ah, bf + nf * 2);
        }
    }

    // ---- epilogue: store fp32 partial (both EPI modes) ----
#pragma unroll
    for (int mf = 0; mf < 4; mf++) {
#pragma unroll
        for (int nf = 0; nf < 4; nf++) {
            const float* cc = acc[mf][nf];
            int row0 = by * 128 + wm + mf * 16 + (lane >> 2);
            int col  = bx * 128 + wn + nf * 8 + (lane & 3) * 2;
            float2 v0 = make_float2(alpha * cc[0], alpha * cc[1]);
            float2 v1 = make_float2(alpha * cc[2], alpha * cc[3]);
            *(float2*)(Cp + (size_t)row0 * ldc + col) = v0;
            *(float2*)(Cp + (size_t)(row0 + 8) * ldc + col) = v1;
        }
    }

    if (EPI == 1) {
        // serial split-K reduction: second-arriving CTA finishes the tile
        __shared__ int s_last;
        __threadfence();
        __syncthreads();
        if (tid == 0)
            s_last = (atomicAdd(&cnt[by * 24 + bx], 1) == 1) ? 1 : 0;
        __syncthreads();
        if (s_last) {
            const float* Co = kz ? Cf0 : Cf1;   // peer partial
#pragma unroll
            for (int mf = 0; mf < 4; mf++) {
#pragma unroll
                for (int nf = 0; nf < 4; nf++) {
                    const float* cc = acc[mf][nf];
                    int row0 = by * 128 + wm + mf * 16 + (lane >> 2);
                    int col  = bx * 128 + wn + nf * 8 + (lane & 3) * 2;
                    float2 o0 = *(const float2*)(Co + (size_t)row0 * ldc + col);
                    float2 o1 = *(const float2*)(Co + (size_t)(row0 + 8) * ldc + col);
                    float b0 = 0.f, b1 = 0.f;
                    if (bias) { b0 = bias[col]; b1 = bias[col + 1]; }
                    float v0 = alpha * cc[0] + o0.x + b0;
                    float v1 = alpha * cc[1] + o0.y + b1;
                    float v2 = alpha * cc[2] + o1.x + b0;
                    float v3 = alpha * cc[3] + o1.y + b1;
                    *(uint32_t*)(Dst + (size_t)row0 * ldc + col) = pack2h(v0, v1);
                    *(uint32_t*)(Dst + (size_t)(row0 + 8) * ldc + col) = pack2h(v2, v3);
                }
            }
            __syncthreads();
            if (tid == 0) cnt[by * 24 + bx] = 0;   // self-reset for next use/replay
        }
    }
}

// ---------------------------------------------------------------------------
// Causal softmax over row i (len = i+1); scores = p0 + p1 (split-K partials);
// writes fp16 weights (zero-padded) and accumulates 0.25*w into out.
// ---------------------------------------------------------------------------
__global__ __launch_bounds__(256) void softmax_causal_acc(
    const float* __restrict__ w0, const float* __restrict__ w1,
    __half* __restrict__ wh, float* __restrict__ out, int first)
{
    const int i = blockIdx.x;
    const int len = i + 1;
    const int tid = threadIdx.x;

    __shared__ float row[NTOK];
    __shared__ float red[256];

    const float* wr0 = w0 + (size_t)i * NTOK;
    const float* wr1 = w1 + (size_t)i * NTOK;

    float m = -3.4e38f;
    for (int j = tid; j < len; j += 256) {
        float v = wr0[j] + wr1[j];
        row[j] = v;
        m = fmaxf(m, v);
    }
    red[tid] = m;
    __syncthreads();
#pragma unroll
    for (int s = 128; s > 0; s >>= 1) {
        if (tid < s) red[tid] = fmaxf(red[tid], red[tid + s]);
        __syncthreads();
    }
    m = red[0];
    __syncthreads();

    float sum = 0.f;
    for (int j = tid; j < len; j += 256) {
        float e = __expf(row[j] - m);   // arg <= 0, bounded
        row[j] = e;
        sum += e;
    }
    red[tid] = sum;
    __syncthreads();
#pragma unroll
    for (int s = 128; s > 0; s >>= 1) {
        if (tid < s) red[tid] += red[tid + s];
        __syncthreads();
    }
    const float inv = 1.0f / red[0];

    float* outr = out + (size_t)i * NTOK;
    __half* hr = wh + (size_t)i * NTOK;
    for (int j = tid; j < NTOK; j += 256) {
        float v = (j < len) ? row[j] * inv : 0.f;
        hr[j] = __float2half_rn(v);
        if (first) outr[j] = 0.25f * v;
        else       outr[j] += 0.25f * v;
    }
}

// ---------------------------------------------------------------------------
// Transpose v slice of qkv:  vT[c, r] = qkv[r, 2E + c]
// ---------------------------------------------------------------------------
__global__ void transpose_v(const __half* __restrict__ q,
                            __half* __restrict__ t)
{
    __shared__ __half sh[32][33];
    const int c0 = blockIdx.x * 32, r0 = blockIdx.y * 32;
    const int tx = threadIdx.x, ty = threadIdx.y;
#pragma unroll
    for (int k = 0; k < 4; k++) {
        int r = ty + k * 8;
        sh[r][tx] = q[(size_t)(r0 + r) * (3 * EDIM) + 2 * EDIM + c0 + tx];
    }
    __syncthreads();
#pragma unroll
    for (int k = 0; k < 4; k++) {
        int cc = ty + k * 8;
        t[(size_t)(c0 + cc) * NTOK + r0 + tx] = sh[tx][cc];
    }
}

// fp32 -> fp16 convert (vectorized by 4)
__global__ void conv_f16(const float* __restrict__ src,
                         __half* __restrict__ dst, int n4)
{
    int idx = blockIdx.x * blockDim.x + threadIdx.x;
    if (idx >= n4) return;
    float4 v = ((const float4*)src)[idx];
    uint2 ph;
    ph.x = pack2h(v.x, v.y); ph.y = pack2h(v.z, v.w);
    ((uint2*)dst)[idx] = ph;
}

// ---------------------------------------------------------------------------
extern "C" void kernel_launch(void* const* d_in, const int* in_sizes, int n_in,
                              void* d_out, int out_size)
{
    const float* mentions = (const float*)d_in[0];  // [2048,1024]
    const float* Wqkv     = (const float*)d_in[1];  // [4,3072,1024]
    const float* bqkv     = (const float*)d_in[2];  // [4,3072]
    const float* Wo       = (const float*)d_in[3];  // [4,1024,1024]
    const float* bo       = (const float*)d_in[4];  // [4,1024]
    float* out            = (float*)d_out;          // [2048,2048]

    __half *x, *qkv, *wh, *vT, *wv, *Wq, *Wl;
    float *p0, *p1;
    int* cnt;
    cudaGetSymbolAddress((void**)&x, g_x);
    cudaGetSymbolAddress((void**)&qkv, g_qkv);
    cudaGetSymbolAddress((void**)&p0, g_p0);  cudaGetSymbolAddress((void**)&p1, g_p1);
    cudaGetSymbolAddress((void**)&wh, g_wh);
    cudaGetSymbolAddress((void**)&vT, g_vT);
    cudaGetSymbolAddress((void**)&wv, g_wv);
    cudaGetSymbolAddress((void**)&Wq, g_Wqkv);
    cudaGetSymbolAddress((void**)&Wl, g_Wo);
    cudaGetSymbolAddress((void**)&cnt, g_cnt);

    cudaFuncSetAttribute(gemm_mma<1, false, false>,
                         cudaFuncAttributeMaxDynamicSharedMemorySize, SMEM_BYTES);
    cudaFuncSetAttribute(gemm_mma<0, true, false>,
                         cudaFuncAttributeMaxDynamicSharedMemorySize, SMEM_BYTES);
    cudaFuncSetAttribute(gemm_mma<1, false, true>,
                         cudaFuncAttributeMaxDynamicSharedMemorySize, SMEM_BYTES);

    const float scale = 1.0f / 32.0f;   // 1/sqrt(1024)

    // Convert weights + input activations to fp16
    {
        int n4 = NLAYER * 3 * EDIM * EDIM / 4;
        conv_f16<<<(n4 + 255) / 256, 256>>>(Wqkv, Wq, n4);
        n4 = NLAYER * EDIM * EDIM / 4;
        conv_f16<<<(n4 + 255) / 256, 256>>>(Wo, Wl, n4);
        n4 = NTOK * EDIM / 4;
        conv_f16<<<(n4 + 255) / 256, 256>>>(mentions, x, n4);
    }

    for (int l = 0; l < NLAYER; l++) {
        const __half* Wqh = Wq + (size_t)l * 3 * EDIM * EDIM;
        const __half* Woh = Wl + (size_t)l * EDIM * EDIM;
        const float* bq = bqkv + (size_t)l * 3 * EDIM;
        const float* bl = bo   + (size_t)l * EDIM;

        // qkv = x @ Wqkv^T + bqkv  (split-K x2, fused reduce -> fp16)
        gemm_mma<1, false, false><<<dim3(24, 16, 2), 256, SMEM_BYTES>>>(
            x, EDIM, Wqh, EDIM, p0, p1, 3 * EDIM, qkv, bq, cnt, EDIM, 1.0f);

        // scores partials = scale * q @ k^T  (split-K x2, lower blocks only)
        gemm_mma<0, true, false><<<dim3(16, 16, 2), 256, SMEM_BYTES>>>(
            qkv, 3 * EDIM, qkv + EDIM, 3 * EDIM, p0, p1, NTOK,
            nullptr, nullptr, cnt, EDIM, scale);

        // softmax (sums partials) -> w fp16, accumulate 0.25*w into out
        softmax_causal_acc<<<NTOK, 256>>>(p0, p1, wh, out, l == 0 ? 1 : 0);

        // vT = transpose of v slice
        transpose_v<<<dim3(EDIM / 32, NTOK / 32), dim3(32, 8)>>>(qkv, vT);

        // wv = w @ v  (split-K x2, K limited, fused reduce -> fp16)
        gemm_mma<1, false, true><<<dim3(8, 16, 2), 256, SMEM_BYTES>>>(
            wh, NTOK, vT, NTOK, p0, p1, EDIM, wv, nullptr, cnt, NTOK, 1.0f);

        // x = wv @ Wo^T + bo  (split-K x2, fused reduce -> fp16)
        gemm_mma<1, false, false><<<dim3(8, 16, 2), 256, SMEM_BYTES>>>(
            wv, EDIM, Woh, EDIM, p0, p1, EDIM, x, bl, cnt, EDIM, 1.0f);
    }
}

// round 11
// speedup vs baseline: 1.0985x; 1.0985x over previous
#include <cuda_runtime.h>
#include <cuda_fp16.h>
#include <stdint.h>
#include <math.h>

#define NTOK 2048
#define EDIM 1024
#define NLAYER 4

// ---------------------------------------------------------------------------
// Scratch (device globals — allocation is forbidden). Pure fp16 operands.
// ---------------------------------------------------------------------------
__device__ __half g_x[NTOK * EDIM];
__device__ __half g_qkv[NTOK * 3 * EDIM];
__device__ float  g_p0[NTOK * 3 * EDIM];   // split-K partial 0 (24MB, reused)
__device__ float  g_p1[NTOK * 3 * EDIM];   // split-K partial 1
__device__ __half g_wh[NTOK * NTOK];
__device__ __half g_vT[EDIM * NTOK];
__device__ __half g_wv[NTOK * EDIM];
__device__ __half g_Wqkv[NLAYER * 3 * EDIM * EDIM];
__device__ __half g_Wo[NLAYER * EDIM * EDIM];

// ---------------------------------------------------------------------------
// Helpers
// ---------------------------------------------------------------------------
__device__ __forceinline__ uint32_t s2u(const void* p) {
    uint32_t a;
    asm("{ .reg .u64 t; cvta.to.shared.u64 t, %1; cvt.u32.u64 %0, t; }" : "=r"(a) : "l"(p));
    return a;
}
#define CPA(sm, gp) \
    asm volatile("cp.async.cg.shared.global [%0], [%1], 16;" :: "r"(sm), "l"(gp))
#define CPA_COMMIT() asm volatile("cp.async.commit_group;")
#define CPA_WAIT2()  asm volatile("cp.async.wait_group 2;")

#define LDSM4(r0, r1, r2, r3, addr)                                          \
    asm volatile("ldmatrix.sync.aligned.m8n8.x4.shared.b16 {%0,%1,%2,%3}, [%4];" \
                 : "=r"(r0), "=r"(r1), "=r"(r2), "=r"(r3) : "r"(addr))

__device__ __forceinline__ void mma16816(float* c, const uint32_t* a, const uint32_t* b) {
    asm volatile(
        "mma.sync.aligned.m16n8k16.row.col.f32.f16.f16.f32 "
        "{%0,%1,%2,%3}, {%4,%5,%6,%7}, {%8,%9}, {%0,%1,%2,%3};"
        : "+f"(c[0]), "+f"(c[1]), "+f"(c[2]), "+f"(c[3])
        : "r"(a[0]), "r"(a[1]), "r"(a[2]), "r"(a[3]), "r"(b[0]), "r"(b[1]));
}

__device__ __forceinline__ uint32_t pack2h(float a, float b) {
    __half2 t = __floats2half2_rn(a, b);
    return *reinterpret_cast<uint32_t*>(&t);
}

// SMEM: 4 stages; stage = 2 tiles (A, B) of 128 rows x 16 fp16,
// 48B pitch (banks 12r mod 32 distinct for r=0..7 -> conflict-free ldmatrix).
// (R8 configuration: best measured. DO NOT TOUCH.)
#define TILE_B   6144          // 128 * 48
#define STAGE_B  12288         // 2 tiles
#define SMEM_BYTES (4 * STAGE_B)   // 49152

// ---------------------------------------------------------------------------
// Split-K (x2) tensor-core NT GEMM, single-pass fp16 (exact R8 kernel):
//   partial[kz] = sum_{k in half kz} A*B^T   (fp32 out)
//   CSKIP: skip blocks strictly above diagonal;  KLIM: Keff = (by+1)*128
// 4-stage cp.async pipeline, ONE __syncthreads per K=16 chunk.
// ---------------------------------------------------------------------------
template<bool CSKIP, bool KLIM>
__global__ void __launch_bounds__(256, 2) gemm_mma(
    const __half* __restrict__ A, int lda,
    const __half* __restrict__ B, int ldb,
    float* __restrict__ Cf0, float* __restrict__ Cf1, int ldc,
    int K, float alpha)
{
    const int bx = blockIdx.x, by = blockIdx.y, kz = blockIdx.z;
    if (CSKIP && bx > by) return;
    const int Keff = KLIM ? min(K, (by + 1) * 128) : K;
    const int half = Keff >> 1;            // multiple of 64
    const int k0   = kz ? half : 0;
    const int nch  = half / 16;            // >= 4 in all uses

    float* __restrict__ Cp = kz ? Cf1 : Cf0;

    extern __shared__ __align__(128) char smem[];
    const uint32_t sb = s2u(smem);

    const int tid  = threadIdx.x;
    const int wid  = tid >> 5, lane = tid & 31;
    const int wm   = (wid & 1) * 64;       // warp m offset (2 warps)
    const int wn   = (wid >> 1) * 32;      // warp n offset (4 warps)

    const __half* Ab = A + (size_t)(by * 128) * lda;
    const __half* Bb = B + (size_t)(bx * 128) * ldb;

    const uint32_t a_row = lane & 15;
    const uint32_t a_k   = (lane >> 4) * 16;
    const uint32_t b_row = (lane & 7) + (lane >> 4) * 8;
    const uint32_t b_k   = ((lane >> 3) & 1) * 16;

    float acc[4][4][4];
#pragma unroll
    for (int i = 0; i < 4; i++)
#pragma unroll
        for (int j = 0; j < 4; j++)
#pragma unroll
            for (int r = 0; r < 4; r++) acc[i][j][r] = 0.f;

    const int lrow = tid >> 1;             // 0..127
    const int lc   = tid & 1;              // 0..1
    const uint32_t lso = (uint32_t)lrow * 48 + lc * 16;
    const size_t   lga = (size_t)lrow * lda + lc * 8;
    const size_t   lgb = (size_t)lrow * ldb + lc * 8;

    auto load_stage = [&](int stage, int kt) {
        uint32_t base = sb + (uint32_t)stage * STAGE_B + lso;
        CPA(base,          Ab + lga + kt);
        CPA(base + TILE_B, Bb + lgb + kt);
    };

#pragma unroll
    for (int s = 0; s < 3; s++) { load_stage(s, k0 + s * 16); CPA_COMMIT(); }

    for (int c = 0; c < nch; c++) {
        CPA_WAIT2();
        __syncthreads();
        if (c + 3 < nch) load_stage((c + 3) & 3, k0 + (c + 3) * 16);
        CPA_COMMIT();

        const uint32_t base = sb + (uint32_t)(c & 3) * STAGE_B;

        uint32_t bf[8];
        {
            uint32_t bb = base + TILE_B + (wn + b_row) * 48 + b_k;
            LDSM4(bf[0], bf[1], bf[2], bf[3], bb);
            LDSM4(bf[4], bf[5], bf[6], bf[7], bb + 16 * 48);
        }
#pragma unroll
        for (int mf = 0; mf < 4; mf++) {
            uint32_t ah[4];
            uint32_t ab = base + (wm + mf * 16 + a_row) * 48 + a_k;
            LDSM4(ah[0], ah[1], ah[2], ah[3], ab);
#pragma unroll
            for (int nf = 0; nf < 4; nf++)
                mma16816(acc[mf][nf], ah, bf + nf * 2);
        }
    }

    // ---- epilogue: fp32 partial ----
#pragma unroll
    for (int mf = 0; mf < 4; mf++) {
#pragma unroll
        for (int nf = 0; nf < 4; nf++) {
            const float* cc = acc[mf][nf];
            int row0 = by * 128 + wm + mf * 16 + (lane >> 2);
            int col  = bx * 128 + wn + nf * 8 + (lane & 3) * 2;
            float2 v0 = make_float2(alpha * cc[0], alpha * cc[1]);
            float2 v1 = make_float2(alpha * cc[2], alpha * cc[3]);
            *(float2*)(Cp + (size_t)row0 * ldc + col) = v0;
            *(float2*)(Cp + (size_t)(row0 + 8) * ldc + col) = v1;
        }
    }
}

// ---------------------------------------------------------------------------
// Fused qkv combine + v transpose. 64x64 tiles over [2048, 3072].
//   qkv = p0 + p1 + bqkv -> fp16 (row-major), and for v-region tiles
//   (c0 >= 2048) also vT[c-2048][r] = qkv[r][c] via smem.
// ---------------------------------------------------------------------------
__global__ __launch_bounds__(256) void combine_qkv_transpose(
    const float* __restrict__ p0, const float* __restrict__ p1,
    const float* __restrict__ bias,
    __half* __restrict__ qkv, __half* __restrict__ vT)
{
    __shared__ __half sh[64][65];
    const int c0 = blockIdx.x * 64, r0 = blockIdx.y * 64;
    const int tid = threadIdx.x;
    const int col4 = tid & 15;         // 16 groups of 4 cols
    const int rbase = tid >> 4;        // 16 rows per sweep
    const bool vtile = (c0 >= 2 * EDIM);

    float b0 = bias[c0 + col4 * 4 + 0];
    float b1 = bias[c0 + col4 * 4 + 1];
    float b2 = bias[c0 + col4 * 4 + 2];
    float b3 = bias[c0 + col4 * 4 + 3];

#pragma unroll
    for (int rr = 0; rr < 4; rr++) {
        int r = rbase + rr * 16;
        size_t idx4 = ((size_t)(r0 + r) * (3 * EDIM) + c0 + col4 * 4) >> 2;
        float4 a = ((const float4*)p0)[idx4];
        float4 b = ((const float4*)p1)[idx4];
        float v0 = a.x + b.x + b0, v1 = a.y + b.y + b1;
        float v2 = a.z + b.z + b2, v3 = a.w + b.w + b3;
        uint2 ph;
        ph.x = pack2h(v0, v1); ph.y = pack2h(v2, v3);
        ((uint2*)qkv)[idx4] = ph;
        if (vtile) {
            __half2 h01 = __floats2half2_rn(v0, v1);
            __half2 h23 = __floats2half2_rn(v2, v3);
            sh[r][col4 * 4 + 0] = __low2half(h01);
            sh[r][col4 * 4 + 1] = __high2half(h01);
            sh[r][col4 * 4 + 2] = __low2half(h23);
            sh[r][col4 * 4 + 3] = __high2half(h23);
        }
    }

    if (vtile) {
        __syncthreads();
        const int cc = tid & 63;       // local v column -> vT row
        const int rg = tid >> 6;       // 4 groups of 16 rows
        __half tmp[16];
#pragma unroll
        for (int j = 0; j < 16; j++) tmp[j] = sh[rg * 16 + j][cc];
        size_t dst = (size_t)(c0 - 2 * EDIM + cc) * NTOK + r0 + rg * 16;
        *(uint4*)(vT + dst)     = *(uint4*)&tmp[0];
        *(uint4*)(vT + dst + 8) = *(uint4*)&tmp[8];
    }
}

// ---------------------------------------------------------------------------
// combine split-K partials: v = p0 + p1 (+ bias[col]); write fp16
// ---------------------------------------------------------------------------
__global__ void combine_split(const float* __restrict__ p0, const float* __restrict__ p1,
                              const float* __restrict__ bias,
                              __half* __restrict__ dst, int ncols, int n4)
{
    int idx = blockIdx.x * blockDim.x + threadIdx.x;
    if (idx >= n4) return;
    float4 a = ((const float4*)p0)[idx];
    float4 b = ((const float4*)p1)[idx];
    float v0 = a.x + b.x, v1 = a.y + b.y, v2 = a.z + b.z, v3 = a.w + b.w;
    if (bias) {
        int col = (idx * 4) % ncols;
        v0 += bias[col]; v1 += bias[col + 1]; v2 += bias[col + 2]; v3 += bias[col + 3];
    }
    uint2 ph;
    ph.x = pack2h(v0, v1); ph.y = pack2h(v2, v3);
    ((uint2*)dst)[idx] = ph;
}

// ---------------------------------------------------------------------------
// Causal softmax over row i (len = i+1); scores = p0 + p1 (split-K partials);
// writes fp16 weights only up to the block-aligned limit the wv GEMM reads
// (Keff = ((i>>7)+1)<<7) and accumulates 0.25*w into out (full row).
// ---------------------------------------------------------------------------
__global__ __launch_bounds__(256) void softmax_causal_acc(
    const float* __restrict__ w0, const float* __restrict__ w1,
    __half* __restrict__ wh, float* __restrict__ out, int first)
{
    const int i = blockIdx.x;
    const int len = i + 1;
    const int limit = ((i >> 7) + 1) << 7;   // block-aligned, >= len
    const int tid = threadIdx.x;

    __shared__ float row[NTOK];
    __shared__ float red[256];

    const float* wr0 = w0 + (size_t)i * NTOK;
    const float* wr1 = w1 + (size_t)i * NTOK;

    float m = -3.4e38f;
    for (int j = tid; j < len; j += 256) {
        float v = wr0[j] + wr1[j];
        row[j] = v;
        m = fmaxf(m, v);
    }
    red[tid] = m;
    __syncthreads();
#pragma unroll
    for (int s = 128; s > 0; s >>= 1) {
        if (tid < s) red[tid] = fmaxf(red[tid], red[tid + s]);
        __syncthreads();
    }
    m = red[0];
    __syncthreads();

    float sum = 0.f;
    for (int j = tid; j < len; j += 256) {
        float e = __expf(row[j] - m);   // arg <= 0, bounded
        row[j] = e;
        sum += e;
    }
    red[tid] = sum;
    __syncthreads();
#pragma unroll
    for (int s = 128; s > 0; s >>= 1) {
        if (tid < s) red[tid] += red[tid + s];
        __syncthreads();
    }
    const float inv = 1.0f / red[0];

    float* outr = out + (size_t)i * NTOK;
    __half* hr = wh + (size_t)i * NTOK;
    for (int j = tid; j < NTOK; j += 256) {
        float v = (j < len) ? row[j] * inv : 0.f;
        if (j < limit) hr[j] = __float2half_rn(v);
        if (first) outr[j] = 0.25f * v;
        else       outr[j] += 0.25f * v;
    }
}

// fp32 -> fp16 convert (vectorized by 4)
__global__ void conv_f16(const float* __restrict__ src,
                         __half* __restrict__ dst, int n4)
{
    int idx = blockIdx.x * blockDim.x + threadIdx.x;
    if (idx >= n4) return;
    float4 v = ((const float4*)src)[idx];
    uint2 ph;
    ph.x = pack2h(v.x, v.y); ph.y = pack2h(v.z, v.w);
    ((uint2*)dst)[idx] = ph;
}

// ---------------------------------------------------------------------------
extern "C" void kernel_launch(void* const* d_in, const int* in_sizes, int n_in,
                              void* d_out, int out_size)
{
    const float* mentions = (const float*)d_in[0];  // [2048,1024]
    const float* Wqkv     = (const float*)d_in[1];  // [4,3072,1024]
    const float* bqkv     = (const float*)d_in[2];  // [4,3072]
    const float* Wo       = (const float*)d_in[3];  // [4,1024,1024]
    const float* bo       = (const float*)d_in[4];  // [4,1024]
    float* out            = (float*)d_out;          // [2048,2048]

    __half *x, *qkv, *wh, *vT, *wv, *Wq, *Wl;
    float *p0, *p1;
    cudaGetSymbolAddress((void**)&x, g_x);
    cudaGetSymbolAddress((void**)&qkv, g_qkv);
    cudaGetSymbolAddress((void**)&p0, g_p0);  cudaGetSymbolAddress((void**)&p1, g_p1);
    cudaGetSymbolAddress((void**)&wh, g_wh);
    cudaGetSymbolAddress((void**)&vT, g_vT);
    cudaGetSymbolAddress((void**)&wv, g_wv);
    cudaGetSymbolAddress((void**)&Wq, g_Wqkv);
    cudaGetSymbolAddress((void**)&Wl, g_Wo);

    cudaFuncSetAttribute(gemm_mma<false, false>,
                         cudaFuncAttributeMaxDynamicSharedMemorySize, SMEM_BYTES);
    cudaFuncSetAttribute(gemm_mma<true, false>,
                         cudaFuncAttributeMaxDynamicSharedMemorySize, SMEM_BYTES);
    cudaFuncSetAttribute(gemm_mma<false, true>,
                         cudaFuncAttributeMaxDynamicSharedMemorySize, SMEM_BYTES);

    const float scale = 1.0f / 32.0f;   // 1/sqrt(1024)

    // Convert weights + input activations to fp16
    {
        int n4 = NLAYER * 3 * EDIM * EDIM / 4;
        conv_f16<<<(n4 + 255) / 256, 256>>>(Wqkv, Wq, n4);
        n4 = NLAYER * EDIM * EDIM / 4;
        conv_f16<<<(n4 + 255) / 256, 256>>>(Wo, Wl, n4);
        n4 = NTOK * EDIM / 4;
        conv_f16<<<(n4 + 255) / 256, 256>>>(mentions, x, n4);
    }

    for (int l = 0; l < NLAYER; l++) {
        const __half* Wqh = Wq + (size_t)l * 3 * EDIM * EDIM;
        const __half* Woh = Wl + (size_t)l * EDIM * EDIM;
        const float* bq = bqkv + (size_t)l * 3 * EDIM;
        const float* bl = bo   + (size_t)l * EDIM;

        // qkv partials = x @ Wqkv^T   (split-K x2)  [2048,3072] fp32
        gemm_mma<false, false><<<dim3(24, 16, 2), 256, SMEM_BYTES>>>(
            x, EDIM, Wqh, EDIM, p0, p1, 3 * EDIM, EDIM, 1.0f);
        // qkv = p0 + p1 + bqkv -> fp16, AND vT for the v slice (fused)
        combine_qkv_transpose<<<dim3(48, 32), 256>>>(p0, p1, bq, qkv, vT);

        // scores partials = scale * q @ k^T  (split-K x2, lower blocks only)
        gemm_mma<true, false><<<dim3(16, 16, 2), 256, SMEM_BYTES>>>(
            qkv, 3 * EDIM, qkv + EDIM, 3 * EDIM, p0, p1, NTOK, EDIM, scale);

        // softmax (sums partials) -> w fp16 (block-aligned), 0.25*w into out
        softmax_causal_acc<<<NTOK, 256>>>(p0, p1, wh, out, l == 0 ? 1 : 0);

        // wv partials = w @ v  (split-K x2, K limited per row-block)
        gemm_mma<false, true><<<dim3(8, 16, 2), 256, SMEM_BYTES>>>(
            wh, NTOK, vT, NTOK, p0, p1, EDIM, NTOK, 1.0f);
        combine_split<<<(NTOK * EDIM / 4 + 255) / 256, 256>>>(
            p0, p1, nullptr, wv, EDIM, NTOK * EDIM / 4);

        // x partials = wv @ Wo^T  (split-K x2)
        gemm_mma<false, false><<<dim3(8, 16, 2), 256, SMEM_BYTES>>>(
            wv, EDIM, Woh, EDIM, p0, p1, EDIM, EDIM, 1.0f);
        combine_split<<<(NTOK * EDIM / 4 + 255) / 256, 256>>>(
            p0, p1, bl, x, EDIM, NTOK * EDIM / 4);
    }
}